// round 15
// baseline (speedup 1.0000x reference)
#include <cuda_runtime.h>

#define Bsz 1024
#define Hsz 2048
#define Asz 18
#define Tsteps 25
#define LSZ (Bsz * Hsz)

// Persistent scratch state (no device allocation allowed).
__device__ float g_mem[5 * LSZ];   // membranes m1..m5
__device__ float g_cur1[LSZ];      // time-invariant layer-1 current
__device__ float g_sA[LSZ];        // spike ping-pong buffers
__device__ float g_sB[LSZ];
__device__ float g_s5[LSZ];        // dedicated layer-5 spike buffer (head input)
__device__ float g_acc[Bsz * Asz]; // accumulated Q
__device__ float g_Wt[4][Hsz * Hsz];          // k-major transposed W2..W5
__device__ unsigned short g_list[Bsz * Hsz];  // per-row ascending active-k lists
__device__ int g_wstart[Bsz * 65];            // per-row window offsets (64 windows of 32 k)

typedef unsigned long long u64;

// ---- packed f32x2 helpers (Blackwell): two independent rn-fp32 ops per instr
__device__ __forceinline__ u64 pack2(float lo, float hi) {
    u64 r;
    asm("mov.b64 %0, {%1, %2};" : "=l"(r) : "f"(lo), "f"(hi));
    return r;
}
__device__ __forceinline__ void fma2(u64& d, u64 a, u64 b) {
    asm("fma.rn.f32x2 %0, %1, %2, %0;" : "+l"(d) : "l"(a), "l"(b));
}
__device__ __forceinline__ void add2(u64& d, u64 w) {
    asm("add.rn.f32x2 %0, %0, %1;" : "+l"(d) : "l"(w));
}
__device__ __forceinline__ float2 unpack2(u64 v) {
    float2 f;
    asm("mov.b64 {%0, %1}, %2;" : "=f"(f.x), "=f"(f.y) : "l"(v));
    return f;
}

// ---------------------------------------------------------------------------
__global__ void init_kernel() {
    int stride = gridDim.x * blockDim.x;
    int i0 = blockIdx.x * blockDim.x + threadIdx.x;
    for (int k = i0; k < 5 * LSZ; k += stride) g_mem[k] = 0.0f;
    for (int k = i0; k < Bsz * Asz; k += stride) g_acc[k] = 0.0f;
}

// 2048x2048 transpose: dst[k][n] = src[n][k].
__global__ void transpose2048(const float* __restrict__ src, float* __restrict__ dst) {
    __shared__ float t[32][33];
    int x = blockIdx.x * 32 + threadIdx.x;       // k
    int y0 = blockIdx.y * 32 + threadIdx.y;      // n
#pragma unroll
    for (int i = 0; i < 32; i += 8)
        t[threadIdx.y + i][threadIdx.x] = src[(size_t)(y0 + i) * Hsz + x];
    __syncthreads();
    int x2 = blockIdx.y * 32 + threadIdx.x;      // n
    int y2 = blockIdx.x * 32 + threadIdx.y;      // k
#pragma unroll
    for (int i = 0; i < 32; i += 8)
        dst[(size_t)(y2 + i) * Hsz + x2] = t[threadIdx.x][threadIdx.y + i];
}

// Layer-1 LIF (t=0 standalone): mem = fma(0.9, mem, cur1); spike; reset. -> sA.
__global__ void lif1_kernel() {
    int i = blockIdx.x * blockDim.x + threadIdx.x;
    float mv = g_mem[i];
    mv = fmaf(0.9f, mv, g_cur1[i]);
    float sp = (mv > 1.0f) ? 1.0f : 0.0f;
    g_mem[i] = mv - sp;
    g_sA[i] = sp;
}

// ---------------------------------------------------------------------------
// Build ascending active-k lists per row (one warp per row), plus per-32k
// window offsets. Ballot/popc compaction preserves ascending k order.
__global__ __launch_bounds__(256) void build_list_kernel(const float* __restrict__ S) {
    int w = (blockIdx.x * blockDim.x + threadIdx.x) >> 5;   // row
    int lane = threadIdx.x & 31;
    if (w >= Bsz) return;
    const float* row = S + (size_t)w * Hsz;
    unsigned short* lst = g_list + (size_t)w * Hsz;
    int* ws = g_wstart + w * 65;
    int cnt = 0;
    for (int c = 0; c < 64; c++) {
        if (lane == 0) ws[c] = cnt;
        float v = row[c * 32 + lane];
        unsigned bal = __ballot_sync(0xffffffffu, v != 0.0f);
        int pre = __popc(bal & ((1u << lane) - 1u));
        if (v != 0.0f) lst[cnt + pre] = (unsigned short)(c * 32 + lane);
        cnt += __popc(bal);
    }
    if (lane == 0) ws[64] = cnt;
}

// ---------------------------------------------------------------------------
// Sparse spike GEMM + LIF: cur[m][n] = sum_{k active in row m, ascending} Wt[k][n]
// + bias[n], then LIF. Bit-identical to the dense fp32 fma chain because
// fma(0,w,acc)==acc exactly and fma(1,w,acc)==rn(acc+w).
// CTA: 128 m x 128 n. 64 double-buffered smem windows of 32 k x 128 n.
#define SGW 32      // k-window
#define SLDW 128    // smem row stride (floats)

__global__ __launch_bounds__(512) void sparse_gemm_lif_kernel(
    const float* __restrict__ Wt,
    const float* __restrict__ bias,
    int mem_layer, int out_sel)
{
    __shared__ float Wsm[2][SGW][SLDW];   // 2 x 16 KB

    const int tid = threadIdx.x;
    const int lane = tid & 31;
    const int wid = tid >> 5;             // 0..15
    const int m0 = blockIdx.y * 128;
    const int n0 = blockIdx.x * 128;

    // window-load coords: idx = tid + i*512; k = idx>>5 (0..31), nq = idx&31
    const int lk0 = tid >> 5;             // i=0 -> k = tid>>5
    const int lnq = tid & 31;

    // 8 m-rows per warp, 4 n-cols per lane: acc[r][0]=(n,n+1), acc[r][1]=(n+2,n+3)
    u64 acc[8][2];
#pragma unroll
    for (int r = 0; r < 8; r++) { acc[r][0] = 0ULL; acc[r][1] = 0ULL; }

    // stage-0 window load
    {
        float4 v0 = *reinterpret_cast<const float4*>(Wt + (size_t)lk0 * Hsz + n0 + lnq * 4);
        float4 v1 = *reinterpret_cast<const float4*>(Wt + (size_t)(lk0 + 16) * Hsz + n0 + lnq * 4);
        *reinterpret_cast<float4*>(&Wsm[0][lk0][lnq * 4]) = v0;
        *reinterpret_cast<float4*>(&Wsm[0][lk0 + 16][lnq * 4]) = v1;
    }
    __syncthreads();

    int s = 0;
    for (int win = 0; win < 64; win++) {
        // prefetch next window into registers
        float4 p0, p1;
        const bool has_next = win < 63;
        if (has_next) {
            size_t kb = (size_t)(win + 1) * SGW;
            p0 = *reinterpret_cast<const float4*>(Wt + (kb + lk0) * Hsz + n0 + lnq * 4);
            p1 = *reinterpret_cast<const float4*>(Wt + (kb + lk0 + 16) * Hsz + n0 + lnq * 4);
        }

        // compute: each warp walks its 8 m-rows' active lists in this window
        const int kbase = win * SGW;
#pragma unroll 1
        for (int r = 0; r < 8; r++) {
            const int m = m0 + wid * 8 + r;
            const int j0 = g_wstart[m * 65 + win];
            const int j1 = g_wstart[m * 65 + win + 1];
            const int cnt = j1 - j0;                       // 0..32
            int myk = 0;
            if (lane < cnt) myk = g_list[(size_t)m * Hsz + j0 + lane];
#pragma unroll 4
            for (int jj = 0; jj < cnt; jj++) {
                int k = __shfl_sync(0xffffffffu, myk, jj) - kbase;
                ulonglong2 w2 = *reinterpret_cast<const ulonglong2*>(&Wsm[s][k][lane * 4]);
                add2(acc[r][0], w2.x);
                add2(acc[r][1], w2.y);
            }
        }

        // drain prefetch into the other buffer
        if (has_next) {
            *reinterpret_cast<float4*>(&Wsm[s ^ 1][lk0][lnq * 4]) = p0;
            *reinterpret_cast<float4*>(&Wsm[s ^ 1][lk0 + 16][lnq * 4]) = p1;
        }
        __syncthreads();
        s ^= 1;
    }

    // epilogue: bias + LIF per m-row over this lane's 4 cols
    float* mem  = g_mem + (size_t)mem_layer * LSZ;
    float* sout = (out_sel == 2) ? (float*)g_s5 : (out_sel ? (float*)g_sB : (float*)g_sA);

    const int cb = n0 + lane * 4;
    float4 bz = *reinterpret_cast<const float4*>(bias + cb);

#pragma unroll
    for (int r = 0; r < 8; r++) {
        const int m = m0 + wid * 8 + r;
        float2 a0 = unpack2(acc[r][0]);
        float2 a1 = unpack2(acc[r][1]);
        float4 c;
        c.x = a0.x + bz.x;
        c.y = a0.y + bz.y;
        c.z = a1.x + bz.z;
        c.w = a1.y + bz.w;
        size_t o = (size_t)m * Hsz + cb;
        float4 mv = *reinterpret_cast<const float4*>(mem + o);
        mv.x = fmaf(0.9f, mv.x, c.x);
        mv.y = fmaf(0.9f, mv.y, c.y);
        mv.z = fmaf(0.9f, mv.z, c.z);
        mv.w = fmaf(0.9f, mv.w, c.w);
        float4 sp;
        sp.x = (mv.x > 1.0f) ? 1.0f : 0.0f;
        sp.y = (mv.y > 1.0f) ? 1.0f : 0.0f;
        sp.z = (mv.z > 1.0f) ? 1.0f : 0.0f;
        sp.w = (mv.w > 1.0f) ? 1.0f : 0.0f;
        mv.x -= sp.x; mv.y -= sp.y; mv.z -= sp.z; mv.w -= sp.w;
        *reinterpret_cast<float4*>(mem + o) = mv;
        *reinterpret_cast<float4*>(sout + o) = sp;
    }
}

// ---------------------------------------------------------------------------
// Dense GEMM+LIF (champion, LDW=132): used only for cur1 = x @ W1^T + b1.
#define BM 128
#define BN 128
#define BK 16
#define LDW 132
#define NTHR 512

__global__ __launch_bounds__(NTHR, 1) void gemm_lif_kernel(
    const float* __restrict__ Aext,
    const float* __restrict__ W,
    const float* __restrict__ bias,
    int K, int mode, int mem_layer, int in_sel, int out_sel)
{
    __shared__ float As[2][BK][LDW];
    __shared__ float Ws[2][BK][LDW];

    const float* A = (in_sel == 2) ? Aext : (in_sel ? (const float*)g_sB : (const float*)g_sA);

    const int tid = threadIdx.x;
    const int m0 = blockIdx.y * BM;
    const int n0 = blockIdx.x * BN;
    const int tx = tid & 31;
    const int ty = tid >> 5;

    const int grow = tid >> 2;
    const int gkq  = tid & 3;

    u64 acc2[4][4];
#pragma unroll
    for (int i = 0; i < 4; i++)
#pragma unroll
        for (int j = 0; j < 4; j++) acc2[i][j] = 0ULL;

    {
        float4 va = *reinterpret_cast<const float4*>(A + (size_t)(m0 + grow) * K + gkq * 4);
        As[0][gkq * 4 + 0][grow] = va.x;
        As[0][gkq * 4 + 1][grow] = va.y;
        As[0][gkq * 4 + 2][grow] = va.z;
        As[0][gkq * 4 + 3][grow] = va.w;
        float4 vw = *reinterpret_cast<const float4*>(W + (size_t)(n0 + grow) * K + gkq * 4);
        Ws[0][gkq * 4 + 0][grow] = vw.x;
        Ws[0][gkq * 4 + 1][grow] = vw.y;
        Ws[0][gkq * 4 + 2][grow] = vw.z;
        Ws[0][gkq * 4 + 3][grow] = vw.w;
    }
    __syncthreads();

    int s = 0;
    for (int k0 = 0; k0 < K; k0 += BK) {
        float4 pa, pw;
        const bool has_next = (k0 + BK) < K;
        if (has_next) {
            pa = *reinterpret_cast<const float4*>(A + (size_t)(m0 + grow) * K + (k0 + BK) + gkq * 4);
            pw = *reinterpret_cast<const float4*>(W + (size_t)(n0 + grow) * K + (k0 + BK) + gkq * 4);
        }

#pragma unroll
        for (int kk = 0; kk < BK; kk++) {
            const ulonglong2* pa2 = reinterpret_cast<const ulonglong2*>(&As[s][kk][ty * 8]);
            ulonglong2 aA = pa2[0];
            ulonglong2 aB = pa2[1];
            u64 ad[4] = {aA.x, aA.y, aB.x, aB.y};

            float4 b0 = *reinterpret_cast<const float4*>(&Ws[s][kk][tx * 4]);
            u64 bd[4];
            bd[0] = pack2(b0.x, b0.x);
            bd[1] = pack2(b0.y, b0.y);
            bd[2] = pack2(b0.z, b0.z);
            bd[3] = pack2(b0.w, b0.w);

#pragma unroll
            for (int i = 0; i < 4; i++)
#pragma unroll
                for (int j = 0; j < 4; j++)
                    fma2(acc2[i][j], ad[i], bd[j]);
        }

        if (has_next) {
            As[s ^ 1][gkq * 4 + 0][grow] = pa.x;
            As[s ^ 1][gkq * 4 + 1][grow] = pa.y;
            As[s ^ 1][gkq * 4 + 2][grow] = pa.z;
            As[s ^ 1][gkq * 4 + 3][grow] = pa.w;
            Ws[s ^ 1][gkq * 4 + 0][grow] = pw.x;
            Ws[s ^ 1][gkq * 4 + 1][grow] = pw.y;
            Ws[s ^ 1][gkq * 4 + 2][grow] = pw.z;
            Ws[s ^ 1][gkq * 4 + 3][grow] = pw.w;
        }
        __syncthreads();
        s ^= 1;
    }

    float* mem  = g_mem + (size_t)mem_layer * LSZ;
    float* sout = (out_sel == 2) ? (float*)g_s5 : (out_sel ? (float*)g_sB : (float*)g_sA);

    const int cb = n0 + tx * 4;
    float4 bz = *reinterpret_cast<const float4*>(bias + cb);

#pragma unroll
    for (int mi = 0; mi < 4; mi++) {
        float2 v0 = unpack2(acc2[mi][0]);
        float2 v1 = unpack2(acc2[mi][1]);
        float2 v2 = unpack2(acc2[mi][2]);
        float2 v3 = unpack2(acc2[mi][3]);
#pragma unroll
        for (int half = 0; half < 2; half++) {
            int row = m0 + ty * 8 + 2 * mi + half;
            float4 c;
            c.x = (half ? v0.y : v0.x) + bz.x;
            c.y = (half ? v1.y : v1.x) + bz.y;
            c.z = (half ? v2.y : v2.x) + bz.z;
            c.w = (half ? v3.y : v3.x) + bz.w;
            size_t o = (size_t)row * Hsz + cb;
            if (mode == 0) {
                *reinterpret_cast<float4*>(g_cur1 + o) = c;
            } else {
                float4 mv = *reinterpret_cast<const float4*>(mem + o);
                mv.x = fmaf(0.9f, mv.x, c.x);
                mv.y = fmaf(0.9f, mv.y, c.y);
                mv.z = fmaf(0.9f, mv.z, c.z);
                mv.w = fmaf(0.9f, mv.w, c.w);
                float4 sp;
                sp.x = (mv.x > 1.0f) ? 1.0f : 0.0f;
                sp.y = (mv.y > 1.0f) ? 1.0f : 0.0f;
                sp.z = (mv.z > 1.0f) ? 1.0f : 0.0f;
                sp.w = (mv.w > 1.0f) ? 1.0f : 0.0f;
                mv.x -= sp.x; mv.y -= sp.y; mv.z -= sp.z; mv.w -= sp.w;
                *reinterpret_cast<float4*>(mem + o) = mv;
                *reinterpret_cast<float4*>(sout + o) = sp;
            }
        }
    }
}

// ---------------------------------------------------------------------------
// Fused: head(t) over g_s5 (CTAs 0..1023) + lif1(t+1) -> g_sA (CTAs 1024..3071).
__global__ __launch_bounds__(256) void fused_head_lif1_kernel(
    const float* __restrict__ Wv, const float* __restrict__ bv,
    const float* __restrict__ Wa, const float* __restrict__ ba)
{
    __shared__ float srow[Hsz];
    __shared__ float outs[19];
    const int tid = threadIdx.x;

    if (blockIdx.x < Bsz) {
        const int b = blockIdx.x;
        for (int k = tid; k < Hsz; k += 256) srow[k] = g_s5[(size_t)b * Hsz + k];
        __syncthreads();

        const int wid = tid >> 5;
        const int lane = tid & 31;
        for (int j = wid; j < 19; j += 8) {
            const float* wr = (j < 18) ? (Wa + (size_t)j * Hsz) : Wv;
            float p = 0.0f;
            for (int k = lane; k < Hsz; k += 32) p = fmaf(srow[k], wr[k], p);
#pragma unroll
            for (int off = 16; off > 0; off >>= 1) p += __shfl_xor_sync(0xffffffffu, p, off);
            if (lane == 0) outs[j] = p + ((j < 18) ? ba[j] : bv[0]);
        }
        __syncthreads();

        if (tid < Asz) {
            float mx = outs[0];
#pragma unroll
            for (int j = 1; j < Asz; j++) mx = fmaxf(mx, outs[j]);
            float q = outs[18] + outs[tid] - mx;
            g_acc[b * Asz + tid] += q;
        }
    } else {
        int i4 = (blockIdx.x - Bsz) * 256 + tid;
        float4 mv = *reinterpret_cast<const float4*>(g_mem + (size_t)i4 * 4);
        float4 cu = *reinterpret_cast<const float4*>(g_cur1 + (size_t)i4 * 4);
        mv.x = fmaf(0.9f, mv.x, cu.x);
        mv.y = fmaf(0.9f, mv.y, cu.y);
        mv.z = fmaf(0.9f, mv.z, cu.z);
        mv.w = fmaf(0.9f, mv.w, cu.w);
        float4 sp;
        sp.x = (mv.x > 1.0f) ? 1.0f : 0.0f;
        sp.y = (mv.y > 1.0f) ? 1.0f : 0.0f;
        sp.z = (mv.z > 1.0f) ? 1.0f : 0.0f;
        sp.w = (mv.w > 1.0f) ? 1.0f : 0.0f;
        mv.x -= sp.x; mv.y -= sp.y; mv.z -= sp.z; mv.w -= sp.w;
        *reinterpret_cast<float4*>(g_mem + (size_t)i4 * 4) = mv;
        *reinterpret_cast<float4*>(g_sA + (size_t)i4 * 4) = sp;
    }
}

// Final head (t = Tsteps-1).
__global__ __launch_bounds__(256) void head_kernel(
    const float* __restrict__ Wv, const float* __restrict__ bv,
    const float* __restrict__ Wa, const float* __restrict__ ba)
{
    __shared__ float srow[Hsz];
    __shared__ float outs[19];
    const int b = blockIdx.x;
    const int tid = threadIdx.x;

    for (int k = tid; k < Hsz; k += 256) srow[k] = g_s5[(size_t)b * Hsz + k];
    __syncthreads();

    const int wid = tid >> 5;
    const int lane = tid & 31;
    for (int j = wid; j < 19; j += 8) {
        const float* wr = (j < 18) ? (Wa + (size_t)j * Hsz) : Wv;
        float p = 0.0f;
        for (int k = lane; k < Hsz; k += 32) p = fmaf(srow[k], wr[k], p);
#pragma unroll
        for (int off = 16; off > 0; off >>= 1) p += __shfl_xor_sync(0xffffffffu, p, off);
        if (lane == 0) outs[j] = p + ((j < 18) ? ba[j] : bv[0]);
    }
    __syncthreads();

    if (tid < Asz) {
        float mx = outs[0];
#pragma unroll
        for (int j = 1; j < Asz; j++) mx = fmaxf(mx, outs[j]);
        float q = outs[18] + outs[tid] - mx;
        g_acc[b * Asz + tid] += q;
    }
}

__global__ void finalize_kernel(float* __restrict__ out) {
    int i = blockIdx.x * blockDim.x + threadIdx.x;
    if (i < Bsz * Asz) out[i] = g_acc[i] / 25.0f;
}

// ---------------------------------------------------------------------------
extern "C" void kernel_launch(void* const* d_in, const int* in_sizes, int n_in,
                              void* d_out, int out_size) {
    (void)in_sizes; (void)n_in; (void)out_size;
    const float* x  = (const float*)d_in[0];
    const float* W1 = (const float*)d_in[1];
    const float* b1 = (const float*)d_in[2];
    const float* W2 = (const float*)d_in[3];
    const float* b2 = (const float*)d_in[4];
    const float* W3 = (const float*)d_in[5];
    const float* b3 = (const float*)d_in[6];
    const float* W4 = (const float*)d_in[7];
    const float* b4 = (const float*)d_in[8];
    const float* W5 = (const float*)d_in[9];
    const float* b5 = (const float*)d_in[10];
    const float* Wv = (const float*)d_in[11];
    const float* bv = (const float*)d_in[12];
    const float* Wa = (const float*)d_in[13];
    const float* ba = (const float*)d_in[14];

    float* Wt2; float* Wt3; float* Wt4; float* Wt5;
    cudaGetSymbolAddress((void**)&Wt2, g_Wt);
    Wt3 = Wt2 + (size_t)Hsz * Hsz;
    Wt4 = Wt3 + (size_t)Hsz * Hsz;
    Wt5 = Wt4 + (size_t)Hsz * Hsz;

    init_kernel<<<512, 256>>>();

    // transpose W2..W5 into k-major
    dim3 tb(32, 8), tg(64, 64);
    transpose2048<<<tg, tb>>>(W2, Wt2);
    transpose2048<<<tg, tb>>>(W3, Wt3);
    transpose2048<<<tg, tb>>>(W4, Wt4);
    transpose2048<<<tg, tb>>>(W5, Wt5);

    dim3 gg(Hsz / BN, Bsz / BM);   // (16, 8) = 128 CTAs

    // cur1 = x @ W1^T + b1 (time-invariant, computed once; dense champion)
    gemm_lif_kernel<<<gg, NTHR>>>(x, W1, b1, 1024, /*mode=*/0, /*mem_layer=*/0,
                                  /*in_sel=*/2, /*out_sel=*/0);

    lif1_kernel<<<LSZ / 256, 256>>>();                                    // t=0 spikes -> sA

    float* sA; float* sB;
    cudaGetSymbolAddress((void**)&sA, g_sA);
    cudaGetSymbolAddress((void**)&sB, g_sB);

    const int FUSED_GRID = Bsz + LSZ / (4 * 256);                         // 1024 + 2048
    for (int t = 0; t < Tsteps; t++) {
        build_list_kernel<<<128, 256>>>(sA);
        sparse_gemm_lif_kernel<<<gg, 512>>>(Wt2, b2, 1, 1);               // sA -> sB
        build_list_kernel<<<128, 256>>>(sB);
        sparse_gemm_lif_kernel<<<gg, 512>>>(Wt3, b3, 2, 0);               // sB -> sA
        build_list_kernel<<<128, 256>>>(sA);
        sparse_gemm_lif_kernel<<<gg, 512>>>(Wt4, b4, 3, 1);               // sA -> sB
        build_list_kernel<<<128, 256>>>(sB);
        sparse_gemm_lif_kernel<<<gg, 512>>>(Wt5, b5, 4, 2);               // sB -> s5
        if (t < Tsteps - 1)
            fused_head_lif1_kernel<<<FUSED_GRID, 256>>>(Wv, bv, Wa, ba);  // head(t) + lif1(t+1)
        else
            head_kernel<<<Bsz, 256>>>(Wv, bv, Wa, ba);                    // final head
    }

    finalize_kernel<<<(Bsz * Asz + 255) / 256, 256>>>((float*)d_out);
}

// round 16
// speedup vs baseline: 1.5802x; 1.5802x over previous
#include <cuda_runtime.h>

#define Bsz 1024
#define Hsz 2048
#define Asz 18
#define Tsteps 25
#define LSZ (Bsz * Hsz)

// Persistent scratch state (no device allocation allowed).
__device__ float g_mem[5 * LSZ];   // membranes m1..m5
__device__ float g_cur1[LSZ];      // time-invariant layer-1 current
__device__ float g_sA[LSZ];        // spike ping-pong buffers
__device__ float g_sB[LSZ];
__device__ float g_s5[LSZ];        // dedicated layer-5 spike buffer (head input)
__device__ float g_acc[Bsz * Asz]; // accumulated Q

typedef unsigned long long u64;

// ---- packed f32x2 helpers (Blackwell): two independent rn-fp32 FMAs per instr
__device__ __forceinline__ u64 pack2(float lo, float hi) {
    u64 r;
    asm("mov.b64 %0, {%1, %2};" : "=l"(r) : "f"(lo), "f"(hi));
    return r;
}
__device__ __forceinline__ void fma2(u64& d, u64 a, u64 b) {
    asm("fma.rn.f32x2 %0, %1, %2, %0;" : "+l"(d) : "l"(a), "l"(b));
}
__device__ __forceinline__ float2 unpack2(u64 v) {
    float2 f;
    asm("mov.b64 {%0, %1}, %2;" : "=f"(f.x), "=f"(f.y) : "l"(v));
    return f;
}

// ---------------------------------------------------------------------------
__global__ void init_kernel() {
    int stride = gridDim.x * blockDim.x;
    int i0 = blockIdx.x * blockDim.x + threadIdx.x;
    for (int k = i0; k < 5 * LSZ; k += stride) g_mem[k] = 0.0f;
    for (int k = i0; k < Bsz * Asz; k += stride) g_acc[k] = 0.0f;
}

// ---------------------------------------------------------------------------
// C[M,N] = A[M,K] @ W[N,K]^T + bias (fp32, per-element serial ascending-k FMA
// chain, two adjacent-m chains packed into one fma.rn.f32x2), optionally fused
// with LIF update. Round-13 champion (LDW=132, regs=98, 186.5us). Epilogue
// modes: 0 = write raw current to g_cur1; 1 = LIF on mem[mem_layer];
// 2 = write cur1 AND do the t=0 layer-1 LIF (mem starts at exactly 0, so
//     fma(0.9, 0, c) == c bitwise; spike = c > 1; mem1 = c - spike).
#define BM 128
#define BN 128
#define BK 16
#define LDW 132
#define NTHR 512

__global__ __launch_bounds__(NTHR, 1) void gemm_lif_kernel(
    const float* __restrict__ Aext,
    const float* __restrict__ W,
    const float* __restrict__ bias,
    int K, int mode, int mem_layer, int in_sel, int out_sel)
{
    __shared__ float As[2][BK][LDW];
    __shared__ float Ws[2][BK][LDW];

    const float* A = (in_sel == 2) ? Aext : (in_sel ? (const float*)g_sB : (const float*)g_sA);

    const int tid = threadIdx.x;
    const int m0 = blockIdx.y * BM;
    const int n0 = blockIdx.x * BN;
    const int tx = tid & 31;   // 0..31 -> N direction (4 cols each)
    const int ty = tid >> 5;   // 0..15 -> M direction (8 rows each)

    // Global-load coordinates: one float4 per array per thread per stage.
    const int grow = tid >> 2;   // 0..127
    const int gkq  = tid & 3;    // 0..3

    // acc2[mi][j]: lo = (row ty*8+2*mi,   col tx*4+j)
    //              hi = (row ty*8+2*mi+1, col tx*4+j)
    u64 acc2[4][4];
#pragma unroll
    for (int i = 0; i < 4; i++)
#pragma unroll
        for (int j = 0; j < 4; j++) acc2[i][j] = 0ULL;

    // ---- stage-0 load
    {
        float4 va = *reinterpret_cast<const float4*>(A + (size_t)(m0 + grow) * K + gkq * 4);
        As[0][gkq * 4 + 0][grow] = va.x;
        As[0][gkq * 4 + 1][grow] = va.y;
        As[0][gkq * 4 + 2][grow] = va.z;
        As[0][gkq * 4 + 3][grow] = va.w;
        float4 vw = *reinterpret_cast<const float4*>(W + (size_t)(n0 + grow) * K + gkq * 4);
        Ws[0][gkq * 4 + 0][grow] = vw.x;
        Ws[0][gkq * 4 + 1][grow] = vw.y;
        Ws[0][gkq * 4 + 2][grow] = vw.z;
        Ws[0][gkq * 4 + 3][grow] = vw.w;
    }
    __syncthreads();

    int s = 0;
    for (int k0 = 0; k0 < K; k0 += BK) {
        // ---- prefetch next tile into registers
        float4 pa, pw;
        const bool has_next = (k0 + BK) < K;
        if (has_next) {
            pa = *reinterpret_cast<const float4*>(A + (size_t)(m0 + grow) * K + (k0 + BK) + gkq * 4);
            pw = *reinterpret_cast<const float4*>(W + (size_t)(n0 + grow) * K + (k0 + BK) + gkq * 4);
        }

        // ---- compute current stage
#pragma unroll
        for (int kk = 0; kk < BK; kk++) {
            // Packed A operands directly from smem (adjacent-m pairs).
            const ulonglong2* pa2 = reinterpret_cast<const ulonglong2*>(&As[s][kk][ty * 8]);
            ulonglong2 aA = pa2[0];
            ulonglong2 aB = pa2[1];
            u64 ad[4] = {aA.x, aA.y, aB.x, aB.y};

            float4 b0 = *reinterpret_cast<const float4*>(&Ws[s][kk][tx * 4]);
            u64 bd[4];
            bd[0] = pack2(b0.x, b0.x);
            bd[1] = pack2(b0.y, b0.y);
            bd[2] = pack2(b0.z, b0.z);
            bd[3] = pack2(b0.w, b0.w);

#pragma unroll
            for (int i = 0; i < 4; i++)
#pragma unroll
                for (int j = 0; j < 4; j++)
                    fma2(acc2[i][j], ad[i], bd[j]);   // serial ascending-k, 2 m-chains/instr
        }

        // ---- drain prefetch into the other buffer
        if (has_next) {
            As[s ^ 1][gkq * 4 + 0][grow] = pa.x;
            As[s ^ 1][gkq * 4 + 1][grow] = pa.y;
            As[s ^ 1][gkq * 4 + 2][grow] = pa.z;
            As[s ^ 1][gkq * 4 + 3][grow] = pa.w;
            Ws[s ^ 1][gkq * 4 + 0][grow] = pw.x;
            Ws[s ^ 1][gkq * 4 + 1][grow] = pw.y;
            Ws[s ^ 1][gkq * 4 + 2][grow] = pw.z;
            Ws[s ^ 1][gkq * 4 + 3][grow] = pw.w;
        }
        __syncthreads();
        s ^= 1;
    }

    // ---- epilogue: bias + (optional) LIF, float4 per row over this thread's 4 cols
    float* mem  = g_mem + (size_t)mem_layer * LSZ;
    float* sout = (out_sel == 2) ? (float*)g_s5 : (out_sel ? (float*)g_sB : (float*)g_sA);

    const int cb = n0 + tx * 4;
    float4 bz = *reinterpret_cast<const float4*>(bias + cb);

#pragma unroll
    for (int mi = 0; mi < 4; mi++) {
        float2 v0 = unpack2(acc2[mi][0]);
        float2 v1 = unpack2(acc2[mi][1]);
        float2 v2 = unpack2(acc2[mi][2]);
        float2 v3 = unpack2(acc2[mi][3]);
#pragma unroll
        for (int half = 0; half < 2; half++) {
            int row = m0 + ty * 8 + 2 * mi + half;
            float4 c;
            c.x = (half ? v0.y : v0.x) + bz.x;
            c.y = (half ? v1.y : v1.x) + bz.y;
            c.z = (half ? v2.y : v2.x) + bz.z;
            c.w = (half ? v3.y : v3.x) + bz.w;
            size_t o = (size_t)row * Hsz + cb;
            if (mode == 0) {
                *reinterpret_cast<float4*>(g_cur1 + o) = c;
            } else if (mode == 2) {
                // t=0 layer-1 LIF fused: mem==0 exactly, so membrane == c.
                *reinterpret_cast<float4*>(g_cur1 + o) = c;
                float4 sp;
                sp.x = (c.x > 1.0f) ? 1.0f : 0.0f;
                sp.y = (c.y > 1.0f) ? 1.0f : 0.0f;
                sp.z = (c.z > 1.0f) ? 1.0f : 0.0f;
                sp.w = (c.w > 1.0f) ? 1.0f : 0.0f;
                float4 mv;
                mv.x = c.x - sp.x; mv.y = c.y - sp.y;
                mv.z = c.z - sp.z; mv.w = c.w - sp.w;
                *reinterpret_cast<float4*>(mem + o) = mv;     // mem_layer = 0
                *reinterpret_cast<float4*>(sout + o) = sp;    // -> g_sA
            } else {
                float4 mv = *reinterpret_cast<const float4*>(mem + o);
                mv.x = fmaf(0.9f, mv.x, c.x);
                mv.y = fmaf(0.9f, mv.y, c.y);
                mv.z = fmaf(0.9f, mv.z, c.z);
                mv.w = fmaf(0.9f, mv.w, c.w);
                float4 sp;
                sp.x = (mv.x > 1.0f) ? 1.0f : 0.0f;
                sp.y = (mv.y > 1.0f) ? 1.0f : 0.0f;
                sp.z = (mv.z > 1.0f) ? 1.0f : 0.0f;
                sp.w = (mv.w > 1.0f) ? 1.0f : 0.0f;
                mv.x -= sp.x; mv.y -= sp.y; mv.z -= sp.z; mv.w -= sp.w;
                *reinterpret_cast<float4*>(mem + o) = mv;
                *reinterpret_cast<float4*>(sout + o) = sp;
            }
        }
    }
}

// ---------------------------------------------------------------------------
// Fused: head(t) over g_s5 (CTAs 0..1023) + lif1(t+1) -> g_sA (CTAs 1024..3071).
// Disjoint data; head reads s5, lif part touches mem1/cur1/sA only.
__global__ __launch_bounds__(256) void fused_head_lif1_kernel(
    const float* __restrict__ Wv, const float* __restrict__ bv,
    const float* __restrict__ Wa, const float* __restrict__ ba)
{
    __shared__ float srow[Hsz];
    __shared__ float outs[19];   // [0..17]=a, [18]=v
    const int tid = threadIdx.x;

    if (blockIdx.x < Bsz) {
        // ---- dueling head for batch row b
        const int b = blockIdx.x;
        for (int k = tid; k < Hsz; k += 256) srow[k] = g_s5[(size_t)b * Hsz + k];
        __syncthreads();

        const int wid = tid >> 5;
        const int lane = tid & 31;
        for (int j = wid; j < 19; j += 8) {
            const float* wr = (j < 18) ? (Wa + (size_t)j * Hsz) : Wv;
            float p = 0.0f;
            for (int k = lane; k < Hsz; k += 32) p = fmaf(srow[k], wr[k], p);
#pragma unroll
            for (int off = 16; off > 0; off >>= 1) p += __shfl_xor_sync(0xffffffffu, p, off);
            if (lane == 0) outs[j] = p + ((j < 18) ? ba[j] : bv[0]);
        }
        __syncthreads();

        if (tid < Asz) {
            float mx = outs[0];
#pragma unroll
            for (int j = 1; j < Asz; j++) mx = fmaxf(mx, outs[j]);
            float q = outs[18] + outs[tid] - mx;
            g_acc[b * Asz + tid] += q;
        }
    } else {
        // ---- layer-1 LIF for next timestep (float4, bit-identical per element)
        int i4 = (blockIdx.x - Bsz) * 256 + tid;     // 0 .. LSZ/4-1
        float4 mv = *reinterpret_cast<const float4*>(g_mem + (size_t)i4 * 4);
        float4 cu = *reinterpret_cast<const float4*>(g_cur1 + (size_t)i4 * 4);
        mv.x = fmaf(0.9f, mv.x, cu.x);
        mv.y = fmaf(0.9f, mv.y, cu.y);
        mv.z = fmaf(0.9f, mv.z, cu.z);
        mv.w = fmaf(0.9f, mv.w, cu.w);
        float4 sp;
        sp.x = (mv.x > 1.0f) ? 1.0f : 0.0f;
        sp.y = (mv.y > 1.0f) ? 1.0f : 0.0f;
        sp.z = (mv.z > 1.0f) ? 1.0f : 0.0f;
        sp.w = (mv.w > 1.0f) ? 1.0f : 0.0f;
        mv.x -= sp.x; mv.y -= sp.y; mv.z -= sp.z; mv.w -= sp.w;
        *reinterpret_cast<float4*>(g_mem + (size_t)i4 * 4) = mv;
        *reinterpret_cast<float4*>(g_sA + (size_t)i4 * 4) = sp;
    }
}

// Final head (t = Tsteps-1).
__global__ __launch_bounds__(256) void head_kernel(
    const float* __restrict__ Wv, const float* __restrict__ bv,
    const float* __restrict__ Wa, const float* __restrict__ ba)
{
    __shared__ float srow[Hsz];
    __shared__ float outs[19];
    const int b = blockIdx.x;
    const int tid = threadIdx.x;

    for (int k = tid; k < Hsz; k += 256) srow[k] = g_s5[(size_t)b * Hsz + k];
    __syncthreads();

    const int wid = tid >> 5;
    const int lane = tid & 31;
    for (int j = wid; j < 19; j += 8) {
        const float* wr = (j < 18) ? (Wa + (size_t)j * Hsz) : Wv;
        float p = 0.0f;
        for (int k = lane; k < Hsz; k += 32) p = fmaf(srow[k], wr[k], p);
#pragma unroll
        for (int off = 16; off > 0; off >>= 1) p += __shfl_xor_sync(0xffffffffu, p, off);
        if (lane == 0) outs[j] = p + ((j < 18) ? ba[j] : bv[0]);
    }
    __syncthreads();

    if (tid < Asz) {
        float mx = outs[0];
#pragma unroll
        for (int j = 1; j < Asz; j++) mx = fmaxf(mx, outs[j]);
        float q = outs[18] + outs[tid] - mx;
        g_acc[b * Asz + tid] += q;
    }
}

__global__ void finalize_kernel(float* __restrict__ out) {
    int i = blockIdx.x * blockDim.x + threadIdx.x;
    if (i < Bsz * Asz) out[i] = g_acc[i] / 25.0f;
}

// ---------------------------------------------------------------------------
extern "C" void kernel_launch(void* const* d_in, const int* in_sizes, int n_in,
                              void* d_out, int out_size) {
    (void)in_sizes; (void)n_in; (void)out_size;
    const float* x  = (const float*)d_in[0];
    const float* W1 = (const float*)d_in[1];
    const float* b1 = (const float*)d_in[2];
    const float* W2 = (const float*)d_in[3];
    const float* b2 = (const float*)d_in[4];
    const float* W3 = (const float*)d_in[5];
    const float* b3 = (const float*)d_in[6];
    const float* W4 = (const float*)d_in[7];
    const float* b4 = (const float*)d_in[8];
    const float* W5 = (const float*)d_in[9];
    const float* b5 = (const float*)d_in[10];
    const float* Wv = (const float*)d_in[11];
    const float* bv = (const float*)d_in[12];
    const float* Wa = (const float*)d_in[13];
    const float* ba = (const float*)d_in[14];

    init_kernel<<<512, 256>>>();

    dim3 gg(Hsz / BN, Bsz / BM);   // (16, 8) = 128 CTAs

    // cur1 = x @ W1^T + b1 (time-invariant), fused with the t=0 layer-1 LIF
    // (membranes exactly zero -> spike = cur1 > 1, mem1 = cur1 - spike). -> sA
    gemm_lif_kernel<<<gg, NTHR>>>(x, W1, b1, 1024, /*mode=*/2, /*mem_layer=*/0,
                                  /*in_sel=*/2, /*out_sel=*/0);

    const int FUSED_GRID = Bsz + LSZ / (4 * 256);                         // 1024 + 2048
    for (int t = 0; t < Tsteps; t++) {
        gemm_lif_kernel<<<gg, NTHR>>>(nullptr, W2, b2, 2048, 1, 1, 0, 1); // sA -> sB
        gemm_lif_kernel<<<gg, NTHR>>>(nullptr, W3, b3, 2048, 1, 2, 1, 0); // sB -> sA
        gemm_lif_kernel<<<gg, NTHR>>>(nullptr, W4, b4, 2048, 1, 3, 0, 1); // sA -> sB
        gemm_lif_kernel<<<gg, NTHR>>>(nullptr, W5, b5, 2048, 1, 4, 1, 2); // sB -> s5
        if (t < Tsteps - 1)
            fused_head_lif1_kernel<<<FUSED_GRID, 256>>>(Wv, bv, Wa, ba);  // head(t) + lif1(t+1)
        else
            head_kernel<<<Bsz, 256>>>(Wv, bv, Wa, ba);                    // final head
    }

    finalize_kernel<<<(Bsz * Asz + 255) / 256, 256>>>((float*)d_out);
}